// round 1
// baseline (speedup 1.0000x reference)
#include <cuda_runtime.h>
#include <cuda_bf16.h>

// SoftIndex: per-row out[s] = cumsum_s( tanh(x[s] - x[s-1]) ), first diff = 0.
// x: [8192, 8192] fp32, out: same shape.
// One CTA per row; 1024 threads x 8 elements; 3-level inclusive scan.

#define S 8192
#define THREADS 1024
#define PER_THREAD 8   // S / THREADS

__global__ __launch_bounds__(THREADS)
void softindex_kernel(const float* __restrict__ x, float* __restrict__ out)
{
    const int row = blockIdx.x;
    const float* __restrict__ xr = x + (size_t)row * S;
    float* __restrict__ orow     = out + (size_t)row * S;

    const int t    = threadIdx.x;
    const int base = t * PER_THREAD;

    // Vectorized load of this thread's 8 elements (two 16B loads, coalesced).
    float4 a = *reinterpret_cast<const float4*>(xr + base);
    float4 b = *reinterpret_cast<const float4*>(xr + base + 4);

    // Previous element for the first diff. For base==0 use v[0] so diff -> 0
    // (matches reference: element 0 of each row contributes tanh(0)=0).
    float prev = (base == 0) ? a.x : xr[base - 1];

    float v[PER_THREAD] = {a.x, a.y, a.z, a.w, b.x, b.y, b.z, b.w};

    // Thread-local inclusive scan of tanh(diffs).
    float s[PER_THREAD];
    float run = 0.0f;
    float p = prev;
#pragma unroll
    for (int i = 0; i < PER_THREAD; i++) {
        run += tanhf(v[i] - p);
        p = v[i];
        s[i] = run;
    }
    const float tot = run;

    // Warp-level inclusive scan of per-thread totals.
    const unsigned lane = t & 31u;
    const unsigned wid  = t >> 5;
    float ws = tot;
#pragma unroll
    for (int off = 1; off < 32; off <<= 1) {
        float n = __shfl_up_sync(0xffffffffu, ws, off);
        if (lane >= (unsigned)off) ws += n;
    }

    // Cross-warp scan via shared memory (32 warp totals).
    __shared__ float warp_tot[THREADS / 32];
    if (lane == 31u) warp_tot[wid] = ws;
    __syncthreads();
    if (wid == 0) {
        float w = warp_tot[lane];
#pragma unroll
        for (int off = 1; off < 32; off <<= 1) {
            float n = __shfl_up_sync(0xffffffffu, w, off);
            if (lane >= (unsigned)off) w += n;
        }
        warp_tot[lane] = w;  // inclusive scan of warp totals
    }
    __syncthreads();

    // Exclusive prefix for this thread = (sum of prior warps) + (prior threads in warp).
    const float prefix = (wid ? warp_tot[wid - 1] : 0.0f) + (ws - tot);

    float4 o0 = make_float4(prefix + s[0], prefix + s[1], prefix + s[2], prefix + s[3]);
    float4 o1 = make_float4(prefix + s[4], prefix + s[5], prefix + s[6], prefix + s[7]);
    *reinterpret_cast<float4*>(orow + base)     = o0;
    *reinterpret_cast<float4*>(orow + base + 4) = o1;
}

extern "C" void kernel_launch(void* const* d_in, const int* in_sizes, int n_in,
                              void* d_out, int out_size)
{
    const float* x = (const float*)d_in[0];
    float* out     = (float*)d_out;
    (void)in_sizes; (void)n_in; (void)out_size;

    softindex_kernel<<<S, THREADS>>>(x, out);
}

// round 2
// speedup vs baseline: 1.0380x; 1.0380x over previous
#include <cuda_runtime.h>
#include <cuda_bf16.h>

// SoftIndex: per-row out[s] = cumsum_s( tanh(x[s] - x[s-1]) ), first diff = 0.
// x: [8192, 8192] fp32, out: same shape.
// One CTA per row; 1024 threads x 8 elements; 3-level inclusive scan.
// R2: fast tanh (ex2.approx + rcp.approx), shfl neighbor, streaming ld/st.

#define S 8192
#define THREADS 1024
#define PER_THREAD 8   // S / THREADS

// tanh(d) = 1 - 2/(exp(2d)+1) = 1 - 2/(ex2(d * 2/ln2) + 1)
// Exact saturation at +/-inf; ~1e-6 abs error per term.
__device__ __forceinline__ float fast_tanh(float d)
{
    float e;
    asm("ex2.approx.f32 %0, %1;" : "=f"(e) : "f"(d * 2.885390081777927f));
    float r;
    asm("rcp.approx.f32 %0, %1;" : "=f"(r) : "f"(e + 1.0f));
    return fmaf(-2.0f, r, 1.0f);
}

__global__ __launch_bounds__(THREADS)
void softindex_kernel(const float* __restrict__ x, float* __restrict__ out)
{
    const int row = blockIdx.x;
    const float* __restrict__ xr = x + (size_t)row * S;
    float* __restrict__ orow     = out + (size_t)row * S;

    const int t    = threadIdx.x;
    const int base = t * PER_THREAD;

    // Vectorized streaming load of this thread's 8 elements (two 16B loads).
    float4 a = __ldcs(reinterpret_cast<const float4*>(xr + base));
    float4 b = __ldcs(reinterpret_cast<const float4*>(xr + base + 4));

    const unsigned lane = t & 31u;
    const unsigned wid  = t >> 5;

    // Previous element (last elem of thread t-1) via shuffle; lane 0 loads it
    // (predicated scalar LDG, hits a line already in flight). base==0 -> diff 0.
    float prev = __shfl_up_sync(0xffffffffu, b.w, 1);
    if (lane == 0u) prev = (base == 0) ? a.x : xr[base - 1];

    float v[PER_THREAD] = {a.x, a.y, a.z, a.w, b.x, b.y, b.z, b.w};

    // Thread-local inclusive scan of tanh(diffs).
    float s[PER_THREAD];
    float run = 0.0f;
    float p = prev;
#pragma unroll
    for (int i = 0; i < PER_THREAD; i++) {
        run += fast_tanh(v[i] - p);
        p = v[i];
        s[i] = run;
    }
    const float tot = run;

    // Warp-level inclusive scan of per-thread totals.
    float ws = tot;
#pragma unroll
    for (int off = 1; off < 32; off <<= 1) {
        float n = __shfl_up_sync(0xffffffffu, ws, off);
        if (lane >= (unsigned)off) ws += n;
    }

    // Cross-warp scan via shared memory (32 warp totals).
    __shared__ float warp_tot[THREADS / 32];
    if (lane == 31u) warp_tot[wid] = ws;
    __syncthreads();
    if (wid == 0) {
        float w = warp_tot[lane];
#pragma unroll
        for (int off = 1; off < 32; off <<= 1) {
            float n = __shfl_up_sync(0xffffffffu, w, off);
            if (lane >= (unsigned)off) w += n;
        }
        warp_tot[lane] = w;  // inclusive scan of warp totals
    }
    __syncthreads();

    // Exclusive prefix for this thread = (sum of prior warps) + (prior threads in warp).
    const float prefix = (wid ? warp_tot[wid - 1] : 0.0f) + (ws - tot);

    float4 o0 = make_float4(prefix + s[0], prefix + s[1], prefix + s[2], prefix + s[3]);
    float4 o1 = make_float4(prefix + s[4], prefix + s[5], prefix + s[6], prefix + s[7]);
    __stcs(reinterpret_cast<float4*>(orow + base),     o0);
    __stcs(reinterpret_cast<float4*>(orow + base + 4), o1);
}

extern "C" void kernel_launch(void* const* d_in, const int* in_sizes, int n_in,
                              void* d_out, int out_size)
{
    const float* x = (const float*)d_in[0];
    float* out     = (float*)d_out;
    (void)in_sizes; (void)n_in; (void)out_size;

    softindex_kernel<<<S, THREADS>>>(x, out);
}